// round 14
// baseline (speedup 1.0000x reference)
#include <cuda_runtime.h>
#include <cuda_fp16.h>
#include <cstdint>
#include <cstddef>

// Problem constants
#define BATCH   16
#define NQ      4096
#define QD      320
#define CD      1024
#define CTX     93
#define TXT     77
#define IMG     16
#define HEADS   8
#define DH      64
#define ID      512
#define MQ      (BATCH*NQ)
#define ATT_SCALE 0.125f

#define TXT_ROWS (BATCH*TXT)
#define TXT_PAD  1280
#define IMG_ROWS (BATCH*IMG)
#define KVW      1024

typedef __half fp16;

// ---------------- scratch ----------------
__device__ fp16 g_A  [MQ * ID];
__device__ fp16 g_x  [MQ * QD];
__device__ fp16 g_Wq [ID * QD];
__device__ fp16 g_Wo [QD * ID];
__device__ fp16 g_Wc [4][ID * CD];
__device__ fp16 g_ct [TXT_PAD * CD];
__device__ fp16 g_ci [IMG_ROWS * CD];
__device__ fp16 g_KVt[TXT_PAD * KVW];
__device__ fp16 g_KVi[IMG_ROWS * KVW];

// ---------------- helpers ----------------
__device__ __forceinline__ uint32_t smem_u32(const void* p) {
    uint32_t a;
    asm("{ .reg .u64 t; cvta.to.shared.u64 t, %1; cvt.u32.u64 %0, t; }"
        : "=r"(a) : "l"(p));
    return a;
}
__device__ __forceinline__ void cp16(uint32_t dst, const void* src) {
    asm volatile("cp.async.cg.shared.global [%0], [%1], 16;" :: "r"(dst), "l"(src));
}
#define CP_COMMIT() asm volatile("cp.async.commit_group;" ::: "memory")
#define CP_WAIT(n)  asm volatile("cp.async.wait_group %0;" :: "n"(n) : "memory")

__device__ __forceinline__ void mma_f16(float* c, const uint32_t* a, const uint32_t* b)
{
    asm volatile(
        "mma.sync.aligned.m16n8k16.row.col.f32.f16.f16.f32 "
        "{%0,%1,%2,%3}, {%4,%5,%6,%7}, {%8,%9}, {%0,%1,%2,%3};"
        : "+f"(c[0]), "+f"(c[1]), "+f"(c[2]), "+f"(c[3])
        : "r"(a[0]), "r"(a[1]), "r"(a[2]), "r"(a[3]), "r"(b[0]), "r"(b[1]));
}
__device__ __forceinline__ void ldm_x4(uint32_t& r0, uint32_t& r1,
                                       uint32_t& r2, uint32_t& r3, uint32_t addr)
{
    asm volatile("ldmatrix.sync.aligned.m8n8.x4.shared.b16 {%0,%1,%2,%3}, [%4];"
                 : "=r"(r0), "=r"(r1), "=r"(r2), "=r"(r3) : "r"(addr));
}
__device__ __forceinline__ uint32_t pack_hi(float a, float b) {
    __half2 p = __floats2half2_rn(a, b);
    return *(uint32_t*)&p;
}

// ---------------- fp16 GEMM: 64x64 tile, 256 threads, 3-stage -------------
// 8 warps, warp tile 16x32 (wm=wid>>1 rows, wn=wid&1 cols).
// blockIdx.z==1 selects the secondary problem (A2/Ch2/M2).
#define GBK 32
#define SSTR 40
#define A_ELEM (64 * SSTR)
#define B_ELEM (64 * SSTR)
#define STAGE_ELEM (A_ELEM + B_ELEM)
#define NSTAGE 3
#define GEMM_SMEM (NSTAGE * STAGE_ELEM * 2)   // 30720 B

__global__ __launch_bounds__(256)
void mma_gemm_kernel(const fp16* __restrict__ Ah,
                     const fp16* __restrict__ W,
                     float* __restrict__ C, fp16* __restrict__ Ch,
                     const float* __restrict__ bias,
                     int M, int N, int K,
                     const fp16* __restrict__ A2, const fp16* __restrict__ W2,
                     fp16* __restrict__ Ch2, int M2)
{
    if (blockIdx.z == 1) {
        if ((int)blockIdx.y * 64 >= M2) return;
        Ah = A2; W = W2; Ch = Ch2; M = M2;
    }

    extern __shared__ fp16 smem[];
    const uint32_t sbase = smem_u32(smem);

    const int tid = threadIdx.x;
    const int wid = tid >> 5;
    const int lid = tid & 31;
    const int grp = lid >> 2;
    const int t4  = lid & 3;
    const int wm  = wid >> 1;        // 0..3 -> rows wm*16
    const int wn  = wid & 1;         // 0..1 -> cols wn*32
    const int m0  = blockIdx.y * 64;
    const int n0  = blockIdx.x * 64;

    const uint32_t aoff = (uint32_t)((lid & 15) * SSTR + (lid >> 4) * 8);
    const uint32_t boff = (uint32_t)((((lid >> 4) << 3) + (lid & 7)) * SSTR
                                     + ((lid >> 3) & 1) * 8);

    float acc[4][4];
    #pragma unroll
    for (int n = 0; n < 4; n++)
        #pragma unroll
        for (int j = 0; j < 4; j++) acc[n][j] = 0.f;

    const int nch = K / GBK;

    auto load_stage = [&](int ch) {
        const int s = ch % NSTAGE;
        const int k0 = ch * GBK;
        const uint32_t base = sbase + (uint32_t)s * STAGE_ELEM * 2;
        {   // A tile: 64 rows x 32 -> 256 16B chunks, 1 per thread
            const int r = tid >> 2, cb = (tid & 3) * 8;
            const uint32_t so = (uint32_t)(r * SSTR + cb) * 2;
            cp16(base + so, Ah + (size_t)(m0 + r) * K + k0 + cb);
        }
        {   // B tile: 64 rows x 32 -> 256 chunks, 1 per thread
            const int r = tid >> 2, cb = (tid & 3) * 8;
            const uint32_t so = (uint32_t)(r * SSTR + cb) * 2;
            cp16(base + A_ELEM * 2 + so, W + (size_t)(n0 + r) * K + k0 + cb);
        }
        CP_COMMIT();
    };

    load_stage(0);
    if (nch > 1) load_stage(1);
    if (nch > 2) load_stage(2);

    for (int ch = 0; ch < nch; ch++) {
        if (ch + 3 <= nch)      { CP_WAIT(2); }
        else if (ch + 2 <= nch) { CP_WAIT(1); }
        else                    { CP_WAIT(0); }
        __syncthreads();

        const int s = ch % NSTAGE;
        const uint32_t Abase = sbase + (uint32_t)s * STAGE_ELEM * 2;
        const uint32_t Bbase = Abase + A_ELEM * 2;

        #pragma unroll
        for (int kk = 0; kk < GBK; kk += 16) {
            uint32_t bh[4][2];
            ldm_x4(bh[0][0], bh[0][1], bh[1][0], bh[1][1],
                   Bbase + ((uint32_t)((wn * 32) * SSTR + kk) + boff) * 2);
            ldm_x4(bh[2][0], bh[2][1], bh[3][0], bh[3][1],
                   Bbase + ((uint32_t)((wn * 32 + 16) * SSTR + kk) + boff) * 2);
            uint32_t ah[4];
            ldm_x4(ah[0], ah[1], ah[2], ah[3],
                   Abase + ((uint32_t)((wm * 16) * SSTR + kk) + aoff) * 2);
            #pragma unroll
            for (int n = 0; n < 4; n++)
                mma_f16(acc[n], ah, bh[n]);
        }
        __syncthreads();
        if (ch + 3 < nch) load_stage(ch + 3);
    }

    const int row0 = m0 + wm * 16 + grp;
    #pragma unroll
    for (int n = 0; n < 4; n++) {
        const int col = n0 + wn * 32 + n * 8 + t4 * 2;
        if (C) {
            float b0 = 0.f, b1 = 0.f;
            if (bias) { b0 = bias[col]; b1 = bias[col + 1]; }
            *(float2*)(C + (size_t)row0 * N + col) =
                make_float2(acc[n][0] + b0, acc[n][1] + b1);
            *(float2*)(C + (size_t)(row0 + 8) * N + col) =
                make_float2(acc[n][2] + b0, acc[n][3] + b1);
        } else {
            *(uint32_t*)(Ch + (size_t)row0 * N + col) = pack_hi(acc[n][0], acc[n][1]);
            *(uint32_t*)(Ch + (size_t)(row0 + 8) * N + col) = pack_hi(acc[n][2], acc[n][3]);
        }
    }
}

// ---------------- mega prep kernel ----------------
#define SEG_CVT (MQ * QD / 4)
#define SEG_WQ  (QD * ID)
#define SEG_WO  (ID * QD)
#define SEG_WC  (4 * CD * ID)
#define SEG_PT  (TXT_PAD * CD / 4)
#define SEG_PI  (IMG_ROWS * CD / 4)
#define PREP_TOTAL (SEG_CVT + SEG_WQ + SEG_WO + SEG_WC + SEG_PT + SEG_PI)

__global__ __launch_bounds__(256)
void prep_kernel(const float* __restrict__ x,
                 const float* __restrict__ Wq, const float* __restrict__ Wo,
                 const float* __restrict__ W0, const float* __restrict__ W1,
                 const float* __restrict__ W2, const float* __restrict__ W3,
                 const float* __restrict__ ctx,
                 fp16* __restrict__ gx, fp16* __restrict__ gWq,
                 fp16* __restrict__ gWo, fp16* __restrict__ gWc,
                 fp16* __restrict__ gct, fp16* __restrict__ gci)
{
    int gid = blockIdx.x * 256 + threadIdx.x;

    if (gid < SEG_CVT) {
        float4 v = ((const float4*)x)[gid];
        ((uint32_t*)gx)[2 * gid]     = pack_hi(v.x, v.y);
        ((uint32_t*)gx)[2 * gid + 1] = pack_hi(v.z, v.w);
        return;
    }
    gid -= SEG_CVT;

    if (gid < SEG_WQ) {
        int k = gid / ID, n = gid % ID;
        gWq[(size_t)n * QD + k] = __float2half_rn(Wq[gid]);
        return;
    }
    gid -= SEG_WQ;

    if (gid < SEG_WO) {
        int k = gid / QD, n = gid % QD;
        gWo[(size_t)n * ID + k] = __float2half_rn(Wo[gid]);
        return;
    }
    gid -= SEG_WO;

    if (gid < SEG_WC) {
        int which = gid / (CD * ID);
        int idx = gid % (CD * ID);
        const float* W = (which == 0) ? W0 : (which == 1) ? W1 : (which == 2) ? W2 : W3;
        int k = idx / ID, n = idx % ID;
        gWc[(size_t)which * ID * CD + (size_t)n * CD + k] = __float2half_rn(W[idx]);
        return;
    }
    gid -= SEG_WC;

    if (gid < SEG_PT) {
        int r = gid / (CD / 4), c4 = gid % (CD / 4);
        float4 v = make_float4(0.f, 0.f, 0.f, 0.f);
        if (r < TXT_ROWS) {
            int b = r / TXT, j = r % TXT;
            v = *(const float4*)(ctx + ((size_t)b * CTX + j) * CD + c4 * 4);
        }
        ((uint32_t*)gct)[2 * gid]     = pack_hi(v.x, v.y);
        ((uint32_t*)gct)[2 * gid + 1] = pack_hi(v.z, v.w);
        return;
    }
    gid -= SEG_PT;

    if (gid < SEG_PI) {
        int r = gid / (CD / 4), c4 = gid % (CD / 4);
        int b = r / IMG, j = r % IMG;
        float4 v = *(const float4*)(ctx + ((size_t)b * CTX + TXT + j) * CD + c4 * 4);
        ((uint32_t*)gci)[2 * gid]     = pack_hi(v.x, v.y);
        ((uint32_t*)gci)[2 * gid + 1] = pack_hi(v.z, v.w);
    }
}

// ---------------- fused Q-proj + attention ----------------
#define AT_THREADS 256
#define QSTR 72
#define PSTR 104
#define SSTR_F 97
#define XSTR 40

#define F_K    0
#define F_V    (F_K + 96*QSTR)
#define F_PH   (F_V + 64*PSTR)
#define F_PIPE (F_PH + 128*PSTR)
#define XSTAGE (128*XSTR)
#define WSTAGE (64*XSTR)
#define PSTAGE (XSTAGE + WSTAGE)
#define PIPE_ELEM (3*PSTAGE)
#define S_ELEM    (128*SSTR_F*2)
#define UNION_ELEM (S_ELEM > PIPE_ELEM ? S_ELEM : PIPE_ELEM)
#define ATT_SMEM  ((F_PIPE + UNION_ELEM) * 2)

__global__ __launch_bounds__(AT_THREADS, 2)
void fused_qattn_kernel(const fp16* __restrict__ x,
                        const fp16* __restrict__ Wq,
                        const fp16* __restrict__ KVt, const fp16* __restrict__ KVi,
                        fp16* __restrict__ Aout,
                        const float* __restrict__ ts_p, const float* __restrict__ is_p)
{
    extern __shared__ fp16 sm[];
    fp16* sK  = sm + F_K;
    fp16* sV  = sm + F_V;
    fp16* sPh = sm + F_PH;
    float* S  = (float*)(sm + F_PIPE);
    const uint32_t sbase = smem_u32(sm);

    const int h = blockIdx.x, b = blockIdx.z;
    const int tid = threadIdx.x;
    const int wid = tid >> 5, lid = tid & 31;
    const int grp = lid >> 2, t4 = lid & 3;
    const int m0w = wid * 16;
    const size_t qrow0 = (size_t)b * NQ + blockIdx.y * 128;

    const uint32_t aoffX = (uint32_t)((lid & 15) * XSTR + (lid >> 4) * 8);
    const uint32_t boffX = (uint32_t)((((lid >> 4) << 3) + (lid & 7)) * XSTR
                                      + ((lid >> 3) & 1) * 8);
    const uint32_t boffK = (uint32_t)((((lid >> 4) << 3) + (lid & 7)) * QSTR
                                      + ((lid >> 3) & 1) * 8);
    const uint32_t aoffP = (uint32_t)((lid & 15) * PSTR + (lid >> 4) * 8);
    const uint32_t boffV = (uint32_t)((((lid >> 4) << 3) + (lid & 7)) * PSTR
                                      + ((lid >> 3) & 1) * 8);

    auto load_stage = [&](int ch) {
        const int s = ch % 3;
        const int k0 = ch * GBK;
        const uint32_t xb = sbase + (F_PIPE + s * PSTAGE) * 2;
        const uint32_t wb = xb + XSTAGE * 2;
        #pragma unroll
        for (int i = 0; i < 2; i++) {
            const int c = tid + i * AT_THREADS;
            const int r = c >> 2, cb = (c & 3) * 8;
            const uint32_t so = (uint32_t)(r * XSTR + cb) * 2;
            cp16(xb + so, x + (qrow0 + r) * QD + k0 + cb);
        }
        {
            const int r = tid >> 2, cb = (tid & 3) * 8;
            const uint32_t so = (uint32_t)(r * XSTR + cb) * 2;
            cp16(wb + so, Wq + (size_t)(h * DH + r) * QD + k0 + cb);
        }
        CP_COMMIT();
    };

    load_stage(0);
    load_stage(1);
    load_stage(2);

    for (int i = tid; i < 96 * 8; i += AT_THREADS) {
        const int r = i >> 3, c = i & 7;
        uint4 vk = make_uint4(0, 0, 0, 0);
        if (r < TXT) {
            vk = *(const uint4*)(KVt + ((size_t)b * TXT + r) * KVW + h * DH + c * 8);
        } else if (r >= 80) {
            vk = *(const uint4*)(KVi + ((size_t)b * IMG + (r - 80)) * KVW + h * DH + c * 8);
        }
        *(uint4*)(sK + r * QSTR + c * 8) = vk;
    }
    for (int i = tid; i < 96 * 32; i += AT_THREADS) {
        const int j = i >> 5, d = (i & 31) * 2;
        __half2 vv = __halves2half2(__float2half_rn(0.f), __float2half_rn(0.f));
        if (j < TXT) {
            vv = *(const __half2*)(KVt + ((size_t)b * TXT + j) * KVW + 512 + h * DH + d);
        } else if (j >= 80) {
            vv = *(const __half2*)(KVi + ((size_t)b * IMG + (j - 80)) * KVW + 512 + h * DH + d);
        }
        sV[d * PSTR + j] = __low2half(vv);
        sV[(d + 1) * PSTR + j] = __high2half(vv);
    }

    float qacc[8][4];
    #pragma unroll
    for (int n = 0; n < 8; n++)
        #pragma unroll
        for (int j = 0; j < 4; j++) qacc[n][j] = 0.f;

    const int nch = QD / GBK;   // 10
    for (int ch = 0; ch < nch; ch++) {
        if (ch + 3 <= nch)      { CP_WAIT(2); }
        else if (ch + 2 <= nch) { CP_WAIT(1); }
        else                    { CP_WAIT(0); }
        __syncthreads();

        const int s = ch % 3;
        const uint32_t Xbase = sbase + (F_PIPE + s * PSTAGE) * 2;
        const uint32_t Wbase = Xbase + XSTAGE * 2;

        #pragma unroll
        for (int kk = 0; kk < GBK; kk += 16) {
            uint32_t ah[4];
            ldm_x4(ah[0], ah[1], ah[2], ah[3],
                   Xbase + ((uint32_t)(m0w * XSTR + kk) + aoffX) * 2);
            #pragma unroll
            for (int np = 0; np < 4; np++) {
                uint32_t b0[2], b1[2];
                ldm_x4(b0[0], b0[1], b1[0], b1[1],
                       Wbase + ((uint32_t)((np * 16) * XSTR + kk) + boffX) * 2);
                mma_f16(qacc[2 * np],     ah, b0);
                mma_f16(qacc[2 * np + 1], ah, b1);
            }
        }
        __syncthreads();
        if (ch + 3 < nch) load_stage(ch + 3);
    }

    uint32_t qah[4][4];
    #pragma unroll
    for (int i = 0; i < 4; i++) {
        qah[i][0] = pack_hi(qacc[2*i][0], qacc[2*i][1]);
        qah[i][1] = pack_hi(qacc[2*i][2], qacc[2*i][3]);
        qah[i][2] = pack_hi(qacc[2*i+1][0], qacc[2*i+1][1]);
        qah[i][3] = pack_hi(qacc[2*i+1][2], qacc[2*i+1][3]);
    }

    {
        float acc[12][4];
        #pragma unroll
        for (int n = 0; n < 12; n++)
            #pragma unroll
            for (int j = 0; j < 4; j++) acc[n][j] = 0.f;

        #pragma unroll
        for (int i = 0; i < 4; i++) {
            const int kk = i * 16;
            #pragma unroll
            for (int np = 0; np < 6; np++) {
                uint32_t b0[2], b1[2];
                ldm_x4(b0[0], b0[1], b1[0], b1[1],
                       sbase + (F_K) * 2 + ((uint32_t)((np * 16) * QSTR + kk) + boffK) * 2);
                mma_f16(acc[2 * np],     qah[i], b0);
                mma_f16(acc[2 * np + 1], qah[i], b1);
            }
        }
        #pragma unroll
        for (int n = 0; n < 12; n++) {
            const int cb = n * 8 + 2 * t4;
            S[(m0w + grp) * SSTR_F + cb]     = acc[n][0] * ATT_SCALE;
            S[(m0w + grp) * SSTR_F + cb + 1] = acc[n][1] * ATT_SCALE;
            S[(m0w + grp + 8) * SSTR_F + cb]     = acc[n][2] * ATT_SCALE;
            S[(m0w + grp + 8) * SSTR_F + cb + 1] = acc[n][3] * ATT_SCALE;
        }
    }
    __syncthreads();

    if (tid < 128) {
        float* Sr = S + tid * SSTR_F;
        float mt = -1e30f, mi = -1e30f;
        for (int j = 0; j < TXT; j++) mt = fmaxf(mt, Sr[j]);
        for (int j = 80; j < 96; j++) mi = fmaxf(mi, Sr[j]);
        float lt = 0.f, li = 0.f;
        for (int j = 0; j < TXT; j++) { float e = __expf(Sr[j] - mt); lt += e; Sr[j] = e; }
        for (int j = 80; j < 96; j++) { float e = __expf(Sr[j] - mi); li += e; Sr[j] = e; }
        const float ct = ts_p[0] / lt;
        const float ci = is_p[0] / li;
        fp16* ph = sPh + tid * PSTR;
        for (int j = 0; j < 96; j++) {
            float p = (j < TXT) ? Sr[j] * ct : ((j >= 80) ? Sr[j] * ci : 0.f);
            ph[j] = __float2half_rn(p);
        }
    }
    __syncthreads();

    {
        float acc[8][4];
        #pragma unroll
        for (int n = 0; n < 8; n++)
            #pragma unroll
            for (int j = 0; j < 4; j++) acc[n][j] = 0.f;

        #pragma unroll
        for (int kk = 0; kk < 96; kk += 16) {
            uint32_t ah[4];
            ldm_x4(ah[0], ah[1], ah[2], ah[3],
                   sbase + (F_PH) * 2 + ((uint32_t)(m0w * PSTR + kk) + aoffP) * 2);
            #pragma unroll
            for (int np = 0; np < 4; np++) {
                uint32_t b0[2], b1[2];
                ldm_x4(b0[0], b0[1], b1[0], b1[1],
                       sbase + (F_V) * 2 + ((uint32_t)((np * 16) * PSTR + kk) + boffV) * 2);
                mma_f16(acc[2 * np],     ah, b0);
                mma_f16(acc[2 * np + 1], ah, b1);
            }
        }
        const size_t rg = qrow0 + m0w + grp;
        #pragma unroll
        for (int n = 0; n < 8; n++) {
            const int col = h * DH + n * 8 + 2 * t4;
            *(uint32_t*)(Aout + rg * ID + col) = pack_hi(acc[n][0], acc[n][1]);
            *(uint32_t*)(Aout + (rg + 8) * ID + col) = pack_hi(acc[n][2], acc[n][3]);
        }
    }
}

// ---------------- launch ----------------
extern "C" void kernel_launch(void* const* d_in, const int* in_sizes, int n_in,
                              void* d_out, int out_size)
{
    const float* x    = (const float*)d_in[0];
    const float* ctx  = (const float*)d_in[1];
    const float* Wq   = (const float*)d_in[2];
    const float* Wk   = (const float*)d_in[3];
    const float* Wv   = (const float*)d_in[4];
    const float* Wkip = (const float*)d_in[5];
    const float* Wvip = (const float*)d_in[6];
    const float* Wo   = (const float*)d_in[7];
    const float* bo   = (const float*)d_in[8];
    const float* ts   = (const float*)d_in[9];
    const float* isc  = (const float*)d_in[10];
    float* out = (float*)d_out;

    fp16 *gA, *gx, *gWq, *gWo, *gWc, *gct, *gci, *gKVt, *gKVi;
    cudaGetSymbolAddress((void**)&gA,   g_A);
    cudaGetSymbolAddress((void**)&gx,   g_x);
    cudaGetSymbolAddress((void**)&gWq,  g_Wq);
    cudaGetSymbolAddress((void**)&gWo,  g_Wo);
    cudaGetSymbolAddress((void**)&gWc,  g_Wc);
    cudaGetSymbolAddress((void**)&gct,  g_ct);
    cudaGetSymbolAddress((void**)&gci,  g_ci);
    cudaGetSymbolAddress((void**)&gKVt, g_KVt);
    cudaGetSymbolAddress((void**)&gKVi, g_KVi);

    cudaFuncSetAttribute(mma_gemm_kernel,
                         cudaFuncAttributeMaxDynamicSharedMemorySize, GEMM_SMEM);
    cudaFuncSetAttribute(fused_qattn_kernel,
                         cudaFuncAttributeMaxDynamicSharedMemorySize, ATT_SMEM);

    // ---- single mega-prep launch
    prep_kernel<<<(PREP_TOTAL + 255) / 256, 256>>>(
        x, Wq, Wo, Wk, Wv, Wkip, Wvip, ctx,
        gx, gWq, gWo, gWc, gct, gci);

    // ---- ctx projections: txt (z=0) + img (z=1) in ONE launch
    {
        dim3 g(KVW / 64, TXT_PAD / 64, 2);
        mma_gemm_kernel<<<g, 256, GEMM_SMEM>>>(
            gct, gWc, nullptr, gKVt, nullptr, TXT_PAD, KVW, CD,
            gci, gWc + 2 * (size_t)ID * CD, gKVi, IMG_ROWS);
    }

    // ---- fused Q-proj + attention (head fastest in grid)
    {
        dim3 g(HEADS, NQ / 128, BATCH);
        fused_qattn_kernel<<<g, AT_THREADS, ATT_SMEM>>>(gx, gWq, gKVt, gKVi,
                                                        gA, ts, isc);
    }

    // ---- out projection (fp32 + bias)
    {
        dim3 g(QD / 64, MQ / 64, 1);
        mma_gemm_kernel<<<g, 256, GEMM_SMEM>>>(gA, gWo, out, nullptr, bo,
                                               MQ, QD, ID,
                                               nullptr, nullptr, nullptr, 0);
    }
}

// round 15
// speedup vs baseline: 1.0026x; 1.0026x over previous
#include <cuda_runtime.h>
#include <cuda_fp16.h>
#include <cstdint>
#include <cstddef>

// Problem constants
#define BATCH   16
#define NQ      4096
#define QD      320
#define CD      1024
#define CTX     93
#define TXT     77
#define IMG     16
#define HEADS   8
#define DH      64
#define ID      512
#define MQ      (BATCH*NQ)
#define ATT_SCALE 0.125f

#define TXT_ROWS (BATCH*TXT)
#define TXT_PAD  1280
#define IMG_ROWS (BATCH*IMG)
#define KVW      1024

typedef __half fp16;

// ---------------- scratch ----------------
__device__ fp16 g_A  [MQ * ID];
__device__ fp16 g_x  [MQ * QD];
__device__ fp16 g_Wq [ID * QD];
__device__ fp16 g_Wo [QD * ID];
__device__ fp16 g_Wc [4][ID * CD];
__device__ fp16 g_ct [TXT_PAD * CD];
__device__ fp16 g_ci [IMG_ROWS * CD];
__device__ fp16 g_KVt[TXT_PAD * KVW];
__device__ fp16 g_KVi[IMG_ROWS * KVW];

// ---------------- helpers ----------------
__device__ __forceinline__ uint32_t smem_u32(const void* p) {
    uint32_t a;
    asm("{ .reg .u64 t; cvta.to.shared.u64 t, %1; cvt.u32.u64 %0, t; }"
        : "=r"(a) : "l"(p));
    return a;
}
__device__ __forceinline__ void cp16(uint32_t dst, const void* src) {
    asm volatile("cp.async.cg.shared.global [%0], [%1], 16;" :: "r"(dst), "l"(src));
}
#define CP_COMMIT() asm volatile("cp.async.commit_group;" ::: "memory")
#define CP_WAIT(n)  asm volatile("cp.async.wait_group %0;" :: "n"(n) : "memory")

__device__ __forceinline__ void mma_f16(float* c, const uint32_t* a, const uint32_t* b)
{
    asm volatile(
        "mma.sync.aligned.m16n8k16.row.col.f32.f16.f16.f32 "
        "{%0,%1,%2,%3}, {%4,%5,%6,%7}, {%8,%9}, {%0,%1,%2,%3};"
        : "+f"(c[0]), "+f"(c[1]), "+f"(c[2]), "+f"(c[3])
        : "r"(a[0]), "r"(a[1]), "r"(a[2]), "r"(a[3]), "r"(b[0]), "r"(b[1]));
}
__device__ __forceinline__ void ldm_x4(uint32_t& r0, uint32_t& r1,
                                       uint32_t& r2, uint32_t& r3, uint32_t addr)
{
    asm volatile("ldmatrix.sync.aligned.m8n8.x4.shared.b16 {%0,%1,%2,%3}, [%4];"
                 : "=r"(r0), "=r"(r1), "=r"(r2), "=r"(r3) : "r"(addr));
}
__device__ __forceinline__ uint32_t pack_hi(float a, float b) {
    __half2 p = __floats2half2_rn(a, b);
    return *(uint32_t*)&p;
}

// ---------------- fp16 GEMM: 128x64 tile, 128 threads, 2-stage ------------
// 4 warps, warp tile 64x32. blockIdx.z==1 selects secondary problem.
// __launch_bounds__(128,6) caps regs at 85 -> 6 blocks/SM (24 warps).
#define GBK 32
#define SSTR 40
#define A_ELEM (128 * SSTR)
#define B_ELEM (64 * SSTR)
#define STAGE_ELEM (A_ELEM + B_ELEM)
#define NSTAGE 2
#define GEMM_SMEM (NSTAGE * STAGE_ELEM * 2)   // 30720 B

__global__ __launch_bounds__(128, 6)
void mma_gemm_kernel(const fp16* __restrict__ Ah,
                     const fp16* __restrict__ W,
                     float* __restrict__ C, fp16* __restrict__ Ch,
                     const float* __restrict__ bias,
                     int M, int N, int K,
                     const fp16* __restrict__ A2, const fp16* __restrict__ W2,
                     fp16* __restrict__ Ch2, int M2)
{
    if (blockIdx.z == 1) {
        if ((int)blockIdx.y * 128 >= M2) return;
        Ah = A2; W = W2; Ch = Ch2; M = M2;
    }

    extern __shared__ fp16 smem[];
    const uint32_t sbase = smem_u32(smem);

    const int tid = threadIdx.x;
    const int wid = tid >> 5;
    const int lid = tid & 31;
    const int grp = lid >> 2;
    const int t4  = lid & 3;
    const int wm  = wid >> 1;
    const int wn  = wid & 1;
    const int m0  = blockIdx.y * 128;
    const int n0  = blockIdx.x * 64;

    const uint32_t aoff = (uint32_t)((lid & 15) * SSTR + (lid >> 4) * 8);
    const uint32_t boff = (uint32_t)((((lid >> 4) << 3) + (lid & 7)) * SSTR
                                     + ((lid >> 3) & 1) * 8);

    float acc[4][4][4];
    #pragma unroll
    for (int m = 0; m < 4; m++)
        #pragma unroll
        for (int n = 0; n < 4; n++)
            #pragma unroll
            for (int j = 0; j < 4; j++) acc[m][n][j] = 0.f;

    const int nch = K / GBK;

    auto load_stage = [&](int ch) {
        const int s = ch % NSTAGE;
        const int k0 = ch * GBK;
        const uint32_t base = sbase + (uint32_t)s * STAGE_ELEM * 2;
        #pragma unroll
        for (int i = 0; i < 4; i++) {
            const int c = tid + i * 128;
            const int r = c >> 2, cb = (c & 3) * 8;
            const uint32_t so = (uint32_t)(r * SSTR + cb) * 2;
            cp16(base + so, Ah + (size_t)(m0 + r) * K + k0 + cb);
        }
        #pragma unroll
        for (int i = 0; i < 2; i++) {
            const int c = tid + i * 128;
            const int r = c >> 2, cb = (c & 3) * 8;
            const uint32_t so = (uint32_t)(r * SSTR + cb) * 2;
            cp16(base + A_ELEM * 2 + so, W + (size_t)(n0 + r) * K + k0 + cb);
        }
        CP_COMMIT();
    };

    load_stage(0);
    if (nch > 1) load_stage(1);

    for (int ch = 0; ch < nch; ch++) {
        if (ch + 2 <= nch) { CP_WAIT(1); } else { CP_WAIT(0); }
        __syncthreads();

        const int s = ch % NSTAGE;
        const uint32_t Abase = sbase + (uint32_t)s * STAGE_ELEM * 2;
        const uint32_t Bbase = Abase + A_ELEM * 2;

        #pragma unroll
        for (int kk = 0; kk < GBK; kk += 16) {
            uint32_t bh[4][2];
            ldm_x4(bh[0][0], bh[0][1], bh[1][0], bh[1][1],
                   Bbase + ((uint32_t)((wn * 32) * SSTR + kk) + boff) * 2);
            ldm_x4(bh[2][0], bh[2][1], bh[3][0], bh[3][1],
                   Bbase + ((uint32_t)((wn * 32 + 16) * SSTR + kk) + boff) * 2);
            #pragma unroll
            for (int m = 0; m < 4; m++) {
                uint32_t ah[4];
                ldm_x4(ah[0], ah[1], ah[2], ah[3],
                       Abase + ((uint32_t)((wm * 64 + m * 16) * SSTR + kk) + aoff) * 2);
                #pragma unroll
                for (int n = 0; n < 4; n++)
                    mma_f16(acc[m][n], ah, bh[n]);
            }
        }
        __syncthreads();
        if (ch + 2 < nch) load_stage(ch + 2);
    }

    #pragma unroll
    for (int m = 0; m < 4; m++) {
        const int row0 = m0 + wm * 64 + m * 16 + grp;
        #pragma unroll
        for (int n = 0; n < 4; n++) {
            const int col = n0 + wn * 32 + n * 8 + t4 * 2;
            if (C) {
                float b0 = 0.f, b1 = 0.f;
                if (bias) { b0 = bias[col]; b1 = bias[col + 1]; }
                *(float2*)(C + (size_t)row0 * N + col) =
                    make_float2(acc[m][n][0] + b0, acc[m][n][1] + b1);
                *(float2*)(C + (size_t)(row0 + 8) * N + col) =
                    make_float2(acc[m][n][2] + b0, acc[m][n][3] + b1);
            } else {
                *(uint32_t*)(Ch + (size_t)row0 * N + col) = pack_hi(acc[m][n][0], acc[m][n][1]);
                *(uint32_t*)(Ch + (size_t)(row0 + 8) * N + col) = pack_hi(acc[m][n][2], acc[m][n][3]);
            }
        }
    }
}

// ---------------- mega prep kernel ----------------
#define SEG_CVT (MQ * QD / 4)
#define SEG_WQ  (QD * ID)
#define SEG_WO  (ID * QD)
#define SEG_WC  (4 * CD * ID)
#define SEG_PT  (TXT_PAD * CD / 4)
#define SEG_PI  (IMG_ROWS * CD / 4)
#define PREP_TOTAL (SEG_CVT + SEG_WQ + SEG_WO + SEG_WC + SEG_PT + SEG_PI)

__global__ __launch_bounds__(256)
void prep_kernel(const float* __restrict__ x,
                 const float* __restrict__ Wq, const float* __restrict__ Wo,
                 const float* __restrict__ W0, const float* __restrict__ W1,
                 const float* __restrict__ W2, const float* __restrict__ W3,
                 const float* __restrict__ ctx,
                 fp16* __restrict__ gx, fp16* __restrict__ gWq,
                 fp16* __restrict__ gWo, fp16* __restrict__ gWc,
                 fp16* __restrict__ gct, fp16* __restrict__ gci)
{
    int gid = blockIdx.x * 256 + threadIdx.x;

    if (gid < SEG_CVT) {
        float4 v = ((const float4*)x)[gid];
        ((uint32_t*)gx)[2 * gid]     = pack_hi(v.x, v.y);
        ((uint32_t*)gx)[2 * gid + 1] = pack_hi(v.z, v.w);
        return;
    }
    gid -= SEG_CVT;

    if (gid < SEG_WQ) {
        int k = gid / ID, n = gid % ID;
        gWq[(size_t)n * QD + k] = __float2half_rn(Wq[gid]);
        return;
    }
    gid -= SEG_WQ;

    if (gid < SEG_WO) {
        int k = gid / QD, n = gid % QD;
        gWo[(size_t)n * ID + k] = __float2half_rn(Wo[gid]);
        return;
    }
    gid -= SEG_WO;

    if (gid < SEG_WC) {
        int which = gid / (CD * ID);
        int idx = gid % (CD * ID);
        const float* W = (which == 0) ? W0 : (which == 1) ? W1 : (which == 2) ? W2 : W3;
        int k = idx / ID, n = idx % ID;
        gWc[(size_t)which * ID * CD + (size_t)n * CD + k] = __float2half_rn(W[idx]);
        return;
    }
    gid -= SEG_WC;

    if (gid < SEG_PT) {
        int r = gid / (CD / 4), c4 = gid % (CD / 4);
        float4 v = make_float4(0.f, 0.f, 0.f, 0.f);
        if (r < TXT_ROWS) {
            int b = r / TXT, j = r % TXT;
            v = *(const float4*)(ctx + ((size_t)b * CTX + j) * CD + c4 * 4);
        }
        ((uint32_t*)gct)[2 * gid]     = pack_hi(v.x, v.y);
        ((uint32_t*)gct)[2 * gid + 1] = pack_hi(v.z, v.w);
        return;
    }
    gid -= SEG_PT;

    if (gid < SEG_PI) {
        int r = gid / (CD / 4), c4 = gid % (CD / 4);
        int b = r / IMG, j = r % IMG;
        float4 v = *(const float4*)(ctx + ((size_t)b * CTX + TXT + j) * CD + c4 * 4);
        ((uint32_t*)gci)[2 * gid]     = pack_hi(v.x, v.y);
        ((uint32_t*)gci)[2 * gid + 1] = pack_hi(v.z, v.w);
    }
}

// ---------------- fused Q-proj + attention ----------------
#define AT_THREADS 256
#define QSTR 72
#define PSTR 104
#define SSTR_F 97
#define XSTR 40

#define F_K    0
#define F_V    (F_K + 96*QSTR)
#define F_PH   (F_V + 64*PSTR)
#define F_PIPE (F_PH + 128*PSTR)
#define XSTAGE (128*XSTR)
#define WSTAGE (64*XSTR)
#define PSTAGE (XSTAGE + WSTAGE)
#define PIPE_ELEM (3*PSTAGE)
#define S_ELEM    (128*SSTR_F*2)
#define UNION_ELEM (S_ELEM > PIPE_ELEM ? S_ELEM : PIPE_ELEM)
#define ATT_SMEM  ((F_PIPE + UNION_ELEM) * 2)

__global__ __launch_bounds__(AT_THREADS, 2)
void fused_qattn_kernel(const fp16* __restrict__ x,
                        const fp16* __restrict__ Wq,
                        const fp16* __restrict__ KVt, const fp16* __restrict__ KVi,
                        fp16* __restrict__ Aout,
                        const float* __restrict__ ts_p, const float* __restrict__ is_p)
{
    extern __shared__ fp16 sm[];
    fp16* sK  = sm + F_K;
    fp16* sV  = sm + F_V;
    fp16* sPh = sm + F_PH;
    float* S  = (float*)(sm + F_PIPE);
    const uint32_t sbase = smem_u32(sm);

    const int h = blockIdx.x, b = blockIdx.z;
    const int tid = threadIdx.x;
    const int wid = tid >> 5, lid = tid & 31;
    const int grp = lid >> 2, t4 = lid & 3;
    const int m0w = wid * 16;
    const size_t qrow0 = (size_t)b * NQ + blockIdx.y * 128;

    const uint32_t aoffX = (uint32_t)((lid & 15) * XSTR + (lid >> 4) * 8);
    const uint32_t boffX = (uint32_t)((((lid >> 4) << 3) + (lid & 7)) * XSTR
                                      + ((lid >> 3) & 1) * 8);
    const uint32_t boffK = (uint32_t)((((lid >> 4) << 3) + (lid & 7)) * QSTR
                                      + ((lid >> 3) & 1) * 8);
    const uint32_t aoffP = (uint32_t)((lid & 15) * PSTR + (lid >> 4) * 8);
    const uint32_t boffV = (uint32_t)((((lid >> 4) << 3) + (lid & 7)) * PSTR
                                      + ((lid >> 3) & 1) * 8);

    auto load_stage = [&](int ch) {
        const int s = ch % 3;
        const int k0 = ch * GBK;
        const uint32_t xb = sbase + (F_PIPE + s * PSTAGE) * 2;
        const uint32_t wb = xb + XSTAGE * 2;
        #pragma unroll
        for (int i = 0; i < 2; i++) {
            const int c = tid + i * AT_THREADS;
            const int r = c >> 2, cb = (c & 3) * 8;
            const uint32_t so = (uint32_t)(r * XSTR + cb) * 2;
            cp16(xb + so, x + (qrow0 + r) * QD + k0 + cb);
        }
        {
            const int r = tid >> 2, cb = (tid & 3) * 8;
            const uint32_t so = (uint32_t)(r * XSTR + cb) * 2;
            cp16(wb + so, Wq + (size_t)(h * DH + r) * QD + k0 + cb);
        }
        CP_COMMIT();
    };

    load_stage(0);
    load_stage(1);
    load_stage(2);

    for (int i = tid; i < 96 * 8; i += AT_THREADS) {
        const int r = i >> 3, c = i & 7;
        uint4 vk = make_uint4(0, 0, 0, 0);
        if (r < TXT) {
            vk = *(const uint4*)(KVt + ((size_t)b * TXT + r) * KVW + h * DH + c * 8);
        } else if (r >= 80) {
            vk = *(const uint4*)(KVi + ((size_t)b * IMG + (r - 80)) * KVW + h * DH + c * 8);
        }
        *(uint4*)(sK + r * QSTR + c * 8) = vk;
    }
    for (int i = tid; i < 96 * 32; i += AT_THREADS) {
        const int j = i >> 5, d = (i & 31) * 2;
        __half2 vv = __halves2half2(__float2half_rn(0.f), __float2half_rn(0.f));
        if (j < TXT) {
            vv = *(const __half2*)(KVt + ((size_t)b * TXT + j) * KVW + 512 + h * DH + d);
        } else if (j >= 80) {
            vv = *(const __half2*)(KVi + ((size_t)b * IMG + (j - 80)) * KVW + 512 + h * DH + d);
        }
        sV[d * PSTR + j] = __low2half(vv);
        sV[(d + 1) * PSTR + j] = __high2half(vv);
    }

    float qacc[8][4];
    #pragma unroll
    for (int n = 0; n < 8; n++)
        #pragma unroll
        for (int j = 0; j < 4; j++) qacc[n][j] = 0.f;

    const int nch = QD / GBK;   // 10
    for (int ch = 0; ch < nch; ch++) {
        if (ch + 3 <= nch)      { CP_WAIT(2); }
        else if (ch + 2 <= nch) { CP_WAIT(1); }
        else                    { CP_WAIT(0); }
        __syncthreads();

        const int s = ch % 3;
        const uint32_t Xbase = sbase + (F_PIPE + s * PSTAGE) * 2;
        const uint32_t Wbase = Xbase + XSTAGE * 2;

        #pragma unroll
        for (int kk = 0; kk < GBK; kk += 16) {
            uint32_t ah[4];
            ldm_x4(ah[0], ah[1], ah[2], ah[3],
                   Xbase + ((uint32_t)(m0w * XSTR + kk) + aoffX) * 2);
            #pragma unroll
            for (int np = 0; np < 4; np++) {
                uint32_t b0[2], b1[2];
                ldm_x4(b0[0], b0[1], b1[0], b1[1],
                       Wbase + ((uint32_t)((np * 16) * XSTR + kk) + boffX) * 2);
                mma_f16(qacc[2 * np],     ah, b0);
                mma_f16(qacc[2 * np + 1], ah, b1);
            }
        }
        __syncthreads();
        if (ch + 3 < nch) load_stage(ch + 3);
    }

    uint32_t qah[4][4];
    #pragma unroll
    for (int i = 0; i < 4; i++) {
        qah[i][0] = pack_hi(qacc[2*i][0], qacc[2*i][1]);
        qah[i][1] = pack_hi(qacc[2*i][2], qacc[2*i][3]);
        qah[i][2] = pack_hi(qacc[2*i+1][0], qacc[2*i+1][1]);
        qah[i][3] = pack_hi(qacc[2*i+1][2], qacc[2*i+1][3]);
    }

    {
        float acc[12][4];
        #pragma unroll
        for (int n = 0; n < 12; n++)
            #pragma unroll
            for (int j = 0; j < 4; j++) acc[n][j] = 0.f;

        #pragma unroll
        for (int i = 0; i < 4; i++) {
            const int kk = i * 16;
            #pragma unroll
            for (int np = 0; np < 6; np++) {
                uint32_t b0[2], b1[2];
                ldm_x4(b0[0], b0[1], b1[0], b1[1],
                       sbase + (F_K) * 2 + ((uint32_t)((np * 16) * QSTR + kk) + boffK) * 2);
                mma_f16(acc[2 * np],     qah[i], b0);
                mma_f16(acc[2 * np + 1], qah[i], b1);
            }
        }
        #pragma unroll
        for (int n = 0; n < 12; n++) {
            const int cb = n * 8 + 2 * t4;
            S[(m0w + grp) * SSTR_F + cb]     = acc[n][0] * ATT_SCALE;
            S[(m0w + grp) * SSTR_F + cb + 1] = acc[n][1] * ATT_SCALE;
            S[(m0w + grp + 8) * SSTR_F + cb]     = acc[n][2] * ATT_SCALE;
            S[(m0w + grp + 8) * SSTR_F + cb + 1] = acc[n][3] * ATT_SCALE;
        }
    }
    __syncthreads();

    if (tid < 128) {
        float* Sr = S + tid * SSTR_F;
        float mt = -1e30f, mi = -1e30f;
        for (int j = 0; j < TXT; j++) mt = fmaxf(mt, Sr[j]);
        for (int j = 80; j < 96; j++) mi = fmaxf(mi, Sr[j]);
        float lt = 0.f, li = 0.f;
        for (int j = 0; j < TXT; j++) { float e = __expf(Sr[j] - mt); lt += e; Sr[j] = e; }
        for (int j = 80; j < 96; j++) { float e = __expf(Sr[j] - mi); li += e; Sr[j] = e; }
        const float ct = ts_p[0] / lt;
        const float ci = is_p[0] / li;
        fp16* ph = sPh + tid * PSTR;
        for (int j = 0; j < 96; j++) {
            float p = (j < TXT) ? Sr[j] * ct : ((j >= 80) ? Sr[j] * ci : 0.f);
            ph[j] = __float2half_rn(p);
        }
    }
    __syncthreads();

    {
        float acc[8][4];
        #pragma unroll
        for (int n = 0; n < 8; n++)
            #pragma unroll
            for (int j = 0; j < 4; j++) acc[n][j] = 0.f;

        #pragma unroll
        for (int kk = 0; kk < 96; kk += 16) {
            uint32_t ah[4];
            ldm_x4(ah[0], ah[1], ah[2], ah[3],
                   sbase + (F_PH) * 2 + ((uint32_t)(m0w * PSTR + kk) + aoffP) * 2);
            #pragma unroll
            for (int np = 0; np < 4; np++) {
                uint32_t b0[2], b1[2];
                ldm_x4(b0[0], b0[1], b1[0], b1[1],
                       sbase + (F_V) * 2 + ((uint32_t)((np * 16) * PSTR + kk) + boffV) * 2);
                mma_f16(acc[2 * np],     ah, b0);
                mma_f16(acc[2 * np + 1], ah, b1);
            }
        }
        const size_t rg = qrow0 + m0w + grp;
        #pragma unroll
        for (int n = 0; n < 8; n++) {
            const int col = h * DH + n * 8 + 2 * t4;
            *(uint32_t*)(Aout + rg * ID + col) = pack_hi(acc[n][0], acc[n][1]);
            *(uint32_t*)(Aout + (rg + 8) * ID + col) = pack_hi(acc[n][2], acc[n][3]);
        }
    }
}

// ---------------- launch ----------------
extern "C" void kernel_launch(void* const* d_in, const int* in_sizes, int n_in,
                              void* d_out, int out_size)
{
    const float* x    = (const float*)d_in[0];
    const float* ctx  = (const float*)d_in[1];
    const float* Wq   = (const float*)d_in[2];
    const float* Wk   = (const float*)d_in[3];
    const float* Wv   = (const float*)d_in[4];
    const float* Wkip = (const float*)d_in[5];
    const float* Wvip = (const float*)d_in[6];
    const float* Wo   = (const float*)d_in[7];
    const float* bo   = (const float*)d_in[8];
    const float* ts   = (const float*)d_in[9];
    const float* isc  = (const float*)d_in[10];
    float* out = (float*)d_out;

    fp16 *gA, *gx, *gWq, *gWo, *gWc, *gct, *gci, *gKVt, *gKVi;
    cudaGetSymbolAddress((void**)&gA,   g_A);
    cudaGetSymbolAddress((void**)&gx,   g_x);
    cudaGetSymbolAddress((void**)&gWq,  g_Wq);
    cudaGetSymbolAddress((void**)&gWo,  g_Wo);
    cudaGetSymbolAddress((void**)&gWc,  g_Wc);
    cudaGetSymbolAddress((void**)&gct,  g_ct);
    cudaGetSymbolAddress((void**)&gci,  g_ci);
    cudaGetSymbolAddress((void**)&gKVt, g_KVt);
    cudaGetSymbolAddress((void**)&gKVi, g_KVi);

    cudaFuncSetAttribute(mma_gemm_kernel,
                         cudaFuncAttributeMaxDynamicSharedMemorySize, GEMM_SMEM);
    cudaFuncSetAttribute(fused_qattn_kernel,
                         cudaFuncAttributeMaxDynamicSharedMemorySize, ATT_SMEM);

    // ---- single mega-prep launch
    prep_kernel<<<(PREP_TOTAL + 255) / 256, 256>>>(
        x, Wq, Wo, Wk, Wv, Wkip, Wvip, ctx,
        gx, gWq, gWo, gWc, gct, gci);

    // ---- ctx projections: txt (z=0) + img (z=1) in ONE launch
    {
        dim3 g(KVW / 64, TXT_PAD / 128, 2);
        mma_gemm_kernel<<<g, 128, GEMM_SMEM>>>(
            gct, gWc, nullptr, gKVt, nullptr, TXT_PAD, KVW, CD,
            gci, gWc + 2 * (size_t)ID * CD, gKVi, IMG_ROWS);
    }

    // ---- fused Q-proj + attention (head fastest in grid)
    {
        dim3 g(HEADS, NQ / 128, BATCH);
        fused_qattn_kernel<<<g, AT_THREADS, ATT_SMEM>>>(gx, gWq, gKVt, gKVi,
                                                        gA, ts, isc);
    }

    // ---- out projection (fp32 + bias)
    {
        dim3 g(QD / 64, MQ / 128, 1);
        mma_gemm_kernel<<<g, 128, GEMM_SMEM>>>(gA, gWo, out, nullptr, bo,
                                               MQ, QD, ID,
                                               nullptr, nullptr, nullptr, 0);
    }
}

// round 16
// speedup vs baseline: 1.0967x; 1.0939x over previous
#include <cuda_runtime.h>
#include <cuda_fp16.h>
#include <cstdint>
#include <cstddef>

// Problem constants
#define BATCH   16
#define NQ      4096
#define QD      320
#define CD      1024
#define CTX     93
#define TXT     77
#define IMG     16
#define HEADS   8
#define DH      64
#define ID      512
#define MQ      (BATCH*NQ)
#define ATT_SCALE 0.125f

#define TXT_ROWS (BATCH*TXT)
#define TXT_PAD  1280
#define IMG_ROWS (BATCH*IMG)
#define KVW      1024

typedef __half fp16;

// ---------------- scratch ----------------
__device__ fp16 g_A  [MQ * ID];
__device__ fp16 g_x  [MQ * QD];
__device__ fp16 g_Wq [ID * QD];
__device__ fp16 g_Wo [QD * ID];
__device__ fp16 g_Wc [4][ID * CD];
__device__ fp16 g_ct [TXT_PAD * CD];
__device__ fp16 g_ci [IMG_ROWS * CD];
__device__ fp16 g_KVt[TXT_PAD * KVW];
__device__ fp16 g_KVi[IMG_ROWS * KVW];

// ---------------- helpers ----------------
__device__ __forceinline__ uint32_t smem_u32(const void* p) {
    uint32_t a;
    asm("{ .reg .u64 t; cvta.to.shared.u64 t, %1; cvt.u32.u64 %0, t; }"
        : "=r"(a) : "l"(p));
    return a;
}
__device__ __forceinline__ void cp16(uint32_t dst, const void* src) {
    asm volatile("cp.async.cg.shared.global [%0], [%1], 16;" :: "r"(dst), "l"(src));
}
#define CP_COMMIT() asm volatile("cp.async.commit_group;" ::: "memory")
#define CP_WAIT(n)  asm volatile("cp.async.wait_group %0;" :: "n"(n) : "memory")

__device__ __forceinline__ void mma_f16(float* c, const uint32_t* a, const uint32_t* b)
{
    asm volatile(
        "mma.sync.aligned.m16n8k16.row.col.f32.f16.f16.f32 "
        "{%0,%1,%2,%3}, {%4,%5,%6,%7}, {%8,%9}, {%0,%1,%2,%3};"
        : "+f"(c[0]), "+f"(c[1]), "+f"(c[2]), "+f"(c[3])
        : "r"(a[0]), "r"(a[1]), "r"(a[2]), "r"(a[3]), "r"(b[0]), "r"(b[1]));
}
__device__ __forceinline__ void ldm_x4(uint32_t& r0, uint32_t& r1,
                                       uint32_t& r2, uint32_t& r3, uint32_t addr)
{
    asm volatile("ldmatrix.sync.aligned.m8n8.x4.shared.b16 {%0,%1,%2,%3}, [%4];"
                 : "=r"(r0), "=r"(r1), "=r"(r2), "=r"(r3) : "r"(addr));
}
__device__ __forceinline__ uint32_t pack_hi(float a, float b) {
    __half2 p = __floats2half2_rn(a, b);
    return *(uint32_t*)&p;
}

// ---------------- fp16 GEMM: 128x64 tile, 128 threads, 2-stage ------------
// 4 warps, warp tile 64x32. __launch_bounds__(128,5): reg budget 102 — the
// natural 94-reg allocation fits with NO spills; 5 blocks/SM (20 warps).
#define GBK 32
#define SSTR 40
#define A_ELEM (128 * SSTR)
#define B_ELEM (64 * SSTR)
#define STAGE_ELEM (A_ELEM + B_ELEM)
#define NSTAGE 2
#define GEMM_SMEM (NSTAGE * STAGE_ELEM * 2)   // 30720 B

__global__ __launch_bounds__(128, 5)
void mma_gemm_kernel(const fp16* __restrict__ Ah,
                     const fp16* __restrict__ W,
                     float* __restrict__ C, fp16* __restrict__ Ch,
                     const float* __restrict__ bias,
                     int M, int N, int K,
                     const fp16* __restrict__ A2, const fp16* __restrict__ W2,
                     fp16* __restrict__ Ch2, int M2)
{
    if (blockIdx.z == 1) {
        if ((int)blockIdx.y * 128 >= M2) return;
        Ah = A2; W = W2; Ch = Ch2; M = M2;
    }

    extern __shared__ fp16 smem[];
    const uint32_t sbase = smem_u32(smem);

    const int tid = threadIdx.x;
    const int wid = tid >> 5;
    const int lid = tid & 31;
    const int grp = lid >> 2;
    const int t4  = lid & 3;
    const int wm  = wid >> 1;
    const int wn  = wid & 1;
    const int m0  = blockIdx.y * 128;
    const int n0  = blockIdx.x * 64;

    const uint32_t aoff = (uint32_t)((lid & 15) * SSTR + (lid >> 4) * 8);
    const uint32_t boff = (uint32_t)((((lid >> 4) << 3) + (lid & 7)) * SSTR
                                     + ((lid >> 3) & 1) * 8);

    float acc[4][4][4];
    #pragma unroll
    for (int m = 0; m < 4; m++)
        #pragma unroll
        for (int n = 0; n < 4; n++)
            #pragma unroll
            for (int j = 0; j < 4; j++) acc[m][n][j] = 0.f;

    const int nch = K / GBK;

    auto load_stage = [&](int ch) {
        const int s = ch % NSTAGE;
        const int k0 = ch * GBK;
        const uint32_t base = sbase + (uint32_t)s * STAGE_ELEM * 2;
        #pragma unroll
        for (int i = 0; i < 4; i++) {
            const int c = tid + i * 128;
            const int r = c >> 2, cb = (c & 3) * 8;
            const uint32_t so = (uint32_t)(r * SSTR + cb) * 2;
            cp16(base + so, Ah + (size_t)(m0 + r) * K + k0 + cb);
        }
        #pragma unroll
        for (int i = 0; i < 2; i++) {
            const int c = tid + i * 128;
            const int r = c >> 2, cb = (c & 3) * 8;
            const uint32_t so = (uint32_t)(r * SSTR + cb) * 2;
            cp16(base + A_ELEM * 2 + so, W + (size_t)(n0 + r) * K + k0 + cb);
        }
        CP_COMMIT();
    };

    load_stage(0);
    if (nch > 1) load_stage(1);

    for (int ch = 0; ch < nch; ch++) {
        if (ch + 2 <= nch) { CP_WAIT(1); } else { CP_WAIT(0); }
        __syncthreads();

        const int s = ch % NSTAGE;
        const uint32_t Abase = sbase + (uint32_t)s * STAGE_ELEM * 2;
        const uint32_t Bbase = Abase + A_ELEM * 2;

        #pragma unroll
        for (int kk = 0; kk < GBK; kk += 16) {
            uint32_t bh[4][2];
            ldm_x4(bh[0][0], bh[0][1], bh[1][0], bh[1][1],
                   Bbase + ((uint32_t)((wn * 32) * SSTR + kk) + boff) * 2);
            ldm_x4(bh[2][0], bh[2][1], bh[3][0], bh[3][1],
                   Bbase + ((uint32_t)((wn * 32 + 16) * SSTR + kk) + boff) * 2);
            #pragma unroll
            for (int m = 0; m < 4; m++) {
                uint32_t ah[4];
                ldm_x4(ah[0], ah[1], ah[2], ah[3],
                       Abase + ((uint32_t)((wm * 64 + m * 16) * SSTR + kk) + aoff) * 2);
                #pragma unroll
                for (int n = 0; n < 4; n++)
                    mma_f16(acc[m][n], ah, bh[n]);
            }
        }
        __syncthreads();
        if (ch + 2 < nch) load_stage(ch + 2);
    }

    #pragma unroll
    for (int m = 0; m < 4; m++) {
        const int row0 = m0 + wm * 64 + m * 16 + grp;
        #pragma unroll
        for (int n = 0; n < 4; n++) {
            const int col = n0 + wn * 32 + n * 8 + t4 * 2;
            if (C) {
                float b0 = 0.f, b1 = 0.f;
                if (bias) { b0 = bias[col]; b1 = bias[col + 1]; }
                *(float2*)(C + (size_t)row0 * N + col) =
                    make_float2(acc[m][n][0] + b0, acc[m][n][1] + b1);
                *(float2*)(C + (size_t)(row0 + 8) * N + col) =
                    make_float2(acc[m][n][2] + b0, acc[m][n][3] + b1);
            } else {
                *(uint32_t*)(Ch + (size_t)row0 * N + col) = pack_hi(acc[m][n][0], acc[m][n][1]);
                *(uint32_t*)(Ch + (size_t)(row0 + 8) * N + col) = pack_hi(acc[m][n][2], acc[m][n][3]);
            }
        }
    }
}

// ---------------- mega prep kernel ----------------
#define SEG_CVT (MQ * QD / 4)
#define SEG_WQ  (QD * ID)
#define SEG_WO  (ID * QD)
#define SEG_WC  (4 * CD * ID)
#define SEG_PT  (TXT_PAD * CD / 4)
#define SEG_PI  (IMG_ROWS * CD / 4)
#define PREP_TOTAL (SEG_CVT + SEG_WQ + SEG_WO + SEG_WC + SEG_PT + SEG_PI)

__global__ __launch_bounds__(256)
void prep_kernel(const float* __restrict__ x,
                 const float* __restrict__ Wq, const float* __restrict__ Wo,
                 const float* __restrict__ W0, const float* __restrict__ W1,
                 const float* __restrict__ W2, const float* __restrict__ W3,
                 const float* __restrict__ ctx,
                 fp16* __restrict__ gx, fp16* __restrict__ gWq,
                 fp16* __restrict__ gWo, fp16* __restrict__ gWc,
                 fp16* __restrict__ gct, fp16* __restrict__ gci)
{
    int gid = blockIdx.x * 256 + threadIdx.x;

    if (gid < SEG_CVT) {
        float4 v = ((const float4*)x)[gid];
        ((uint32_t*)gx)[2 * gid]     = pack_hi(v.x, v.y);
        ((uint32_t*)gx)[2 * gid + 1] = pack_hi(v.z, v.w);
        return;
    }
    gid -= SEG_CVT;

    if (gid < SEG_WQ) {
        int k = gid / ID, n = gid % ID;
        gWq[(size_t)n * QD + k] = __float2half_rn(Wq[gid]);
        return;
    }
    gid -= SEG_WQ;

    if (gid < SEG_WO) {
        int k = gid / QD, n = gid % QD;
        gWo[(size_t)n * ID + k] = __float2half_rn(Wo[gid]);
        return;
    }
    gid -= SEG_WO;

    if (gid < SEG_WC) {
        int which = gid / (CD * ID);
        int idx = gid % (CD * ID);
        const float* W = (which == 0) ? W0 : (which == 1) ? W1 : (which == 2) ? W2 : W3;
        int k = idx / ID, n = idx % ID;
        gWc[(size_t)which * ID * CD + (size_t)n * CD + k] = __float2half_rn(W[idx]);
        return;
    }
    gid -= SEG_WC;

    if (gid < SEG_PT) {
        int r = gid / (CD / 4), c4 = gid % (CD / 4);
        float4 v = make_float4(0.f, 0.f, 0.f, 0.f);
        if (r < TXT_ROWS) {
            int b = r / TXT, j = r % TXT;
            v = *(const float4*)(ctx + ((size_t)b * CTX + j) * CD + c4 * 4);
        }
        ((uint32_t*)gct)[2 * gid]     = pack_hi(v.x, v.y);
        ((uint32_t*)gct)[2 * gid + 1] = pack_hi(v.z, v.w);
        return;
    }
    gid -= SEG_PT;

    if (gid < SEG_PI) {
        int r = gid / (CD / 4), c4 = gid % (CD / 4);
        int b = r / IMG, j = r % IMG;
        float4 v = *(const float4*)(ctx + ((size_t)b * CTX + TXT + j) * CD + c4 * 4);
        ((uint32_t*)gci)[2 * gid]     = pack_hi(v.x, v.y);
        ((uint32_t*)gci)[2 * gid + 1] = pack_hi(v.z, v.w);
    }
}

// ---------------- fused Q-proj + attention ----------------
#define AT_THREADS 256
#define QSTR 72
#define PSTR 104
#define SSTR_F 97
#define XSTR 40

#define F_K    0
#define F_V    (F_K + 96*QSTR)
#define F_PH   (F_V + 64*PSTR)
#define F_PIPE (F_PH + 128*PSTR)
#define XSTAGE (128*XSTR)
#define WSTAGE (64*XSTR)
#define PSTAGE (XSTAGE + WSTAGE)
#define PIPE_ELEM (3*PSTAGE)
#define S_ELEM    (128*SSTR_F*2)
#define UNION_ELEM (S_ELEM > PIPE_ELEM ? S_ELEM : PIPE_ELEM)
#define ATT_SMEM  ((F_PIPE + UNION_ELEM) * 2)

__global__ __launch_bounds__(AT_THREADS, 2)
void fused_qattn_kernel(const fp16* __restrict__ x,
                        const fp16* __restrict__ Wq,
                        const fp16* __restrict__ KVt, const fp16* __restrict__ KVi,
                        fp16* __restrict__ Aout,
                        const float* __restrict__ ts_p, const float* __restrict__ is_p)
{
    extern __shared__ fp16 sm[];
    fp16* sK  = sm + F_K;
    fp16* sV  = sm + F_V;
    fp16* sPh = sm + F_PH;
    float* S  = (float*)(sm + F_PIPE);
    const uint32_t sbase = smem_u32(sm);

    const int h = blockIdx.x, b = blockIdx.z;
    const int tid = threadIdx.x;
    const int wid = tid >> 5, lid = tid & 31;
    const int grp = lid >> 2, t4 = lid & 3;
    const int m0w = wid * 16;
    const size_t qrow0 = (size_t)b * NQ + blockIdx.y * 128;

    const uint32_t aoffX = (uint32_t)((lid & 15) * XSTR + (lid >> 4) * 8);
    const uint32_t boffX = (uint32_t)((((lid >> 4) << 3) + (lid & 7)) * XSTR
                                      + ((lid >> 3) & 1) * 8);
    const uint32_t boffK = (uint32_t)((((lid >> 4) << 3) + (lid & 7)) * QSTR
                                      + ((lid >> 3) & 1) * 8);
    const uint32_t aoffP = (uint32_t)((lid & 15) * PSTR + (lid >> 4) * 8);
    const uint32_t boffV = (uint32_t)((((lid >> 4) << 3) + (lid & 7)) * PSTR
                                      + ((lid >> 3) & 1) * 8);

    auto load_stage = [&](int ch) {
        const int s = ch % 3;
        const int k0 = ch * GBK;
        const uint32_t xb = sbase + (F_PIPE + s * PSTAGE) * 2;
        const uint32_t wb = xb + XSTAGE * 2;
        #pragma unroll
        for (int i = 0; i < 2; i++) {
            const int c = tid + i * AT_THREADS;
            const int r = c >> 2, cb = (c & 3) * 8;
            const uint32_t so = (uint32_t)(r * XSTR + cb) * 2;
            cp16(xb + so, x + (qrow0 + r) * QD + k0 + cb);
        }
        {
            const int r = tid >> 2, cb = (tid & 3) * 8;
            const uint32_t so = (uint32_t)(r * XSTR + cb) * 2;
            cp16(wb + so, Wq + (size_t)(h * DH + r) * QD + k0 + cb);
        }
        CP_COMMIT();
    };

    load_stage(0);
    load_stage(1);
    load_stage(2);

    for (int i = tid; i < 96 * 8; i += AT_THREADS) {
        const int r = i >> 3, c = i & 7;
        uint4 vk = make_uint4(0, 0, 0, 0);
        if (r < TXT) {
            vk = *(const uint4*)(KVt + ((size_t)b * TXT + r) * KVW + h * DH + c * 8);
        } else if (r >= 80) {
            vk = *(const uint4*)(KVi + ((size_t)b * IMG + (r - 80)) * KVW + h * DH + c * 8);
        }
        *(uint4*)(sK + r * QSTR + c * 8) = vk;
    }
    for (int i = tid; i < 96 * 32; i += AT_THREADS) {
        const int j = i >> 5, d = (i & 31) * 2;
        __half2 vv = __halves2half2(__float2half_rn(0.f), __float2half_rn(0.f));
        if (j < TXT) {
            vv = *(const __half2*)(KVt + ((size_t)b * TXT + j) * KVW + 512 + h * DH + d);
        } else if (j >= 80) {
            vv = *(const __half2*)(KVi + ((size_t)b * IMG + (j - 80)) * KVW + 512 + h * DH + d);
        }
        sV[d * PSTR + j] = __low2half(vv);
        sV[(d + 1) * PSTR + j] = __high2half(vv);
    }

    float qacc[8][4];
    #pragma unroll
    for (int n = 0; n < 8; n++)
        #pragma unroll
        for (int j = 0; j < 4; j++) qacc[n][j] = 0.f;

    const int nch = QD / GBK;   // 10
    for (int ch = 0; ch < nch; ch++) {
        if (ch + 3 <= nch)      { CP_WAIT(2); }
        else if (ch + 2 <= nch) { CP_WAIT(1); }
        else                    { CP_WAIT(0); }
        __syncthreads();

        const int s = ch % 3;
        const uint32_t Xbase = sbase + (F_PIPE + s * PSTAGE) * 2;
        const uint32_t Wbase = Xbase + XSTAGE * 2;

        #pragma unroll
        for (int kk = 0; kk < GBK; kk += 16) {
            uint32_t ah[4];
            ldm_x4(ah[0], ah[1], ah[2], ah[3],
                   Xbase + ((uint32_t)(m0w * XSTR + kk) + aoffX) * 2);
            #pragma unroll
            for (int np = 0; np < 4; np++) {
                uint32_t b0[2], b1[2];
                ldm_x4(b0[0], b0[1], b1[0], b1[1],
                       Wbase + ((uint32_t)((np * 16) * XSTR + kk) + boffX) * 2);
                mma_f16(qacc[2 * np],     ah, b0);
                mma_f16(qacc[2 * np + 1], ah, b1);
            }
        }
        __syncthreads();
        if (ch + 3 < nch) load_stage(ch + 3);
    }

    uint32_t qah[4][4];
    #pragma unroll
    for (int i = 0; i < 4; i++) {
        qah[i][0] = pack_hi(qacc[2*i][0], qacc[2*i][1]);
        qah[i][1] = pack_hi(qacc[2*i][2], qacc[2*i][3]);
        qah[i][2] = pack_hi(qacc[2*i+1][0], qacc[2*i+1][1]);
        qah[i][3] = pack_hi(qacc[2*i+1][2], qacc[2*i+1][3]);
    }

    {
        float acc[12][4];
        #pragma unroll
        for (int n = 0; n < 12; n++)
            #pragma unroll
            for (int j = 0; j < 4; j++) acc[n][j] = 0.f;

        #pragma unroll
        for (int i = 0; i < 4; i++) {
            const int kk = i * 16;
            #pragma unroll
            for (int np = 0; np < 6; np++) {
                uint32_t b0[2], b1[2];
                ldm_x4(b0[0], b0[1], b1[0], b1[1],
                       sbase + (F_K) * 2 + ((uint32_t)((np * 16) * QSTR + kk) + boffK) * 2);
                mma_f16(acc[2 * np],     qah[i], b0);
                mma_f16(acc[2 * np + 1], qah[i], b1);
            }
        }
        #pragma unroll
        for (int n = 0; n < 12; n++) {
            const int cb = n * 8 + 2 * t4;
            S[(m0w + grp) * SSTR_F + cb]     = acc[n][0] * ATT_SCALE;
            S[(m0w + grp) * SSTR_F + cb + 1] = acc[n][1] * ATT_SCALE;
            S[(m0w + grp + 8) * SSTR_F + cb]     = acc[n][2] * ATT_SCALE;
            S[(m0w + grp + 8) * SSTR_F + cb + 1] = acc[n][3] * ATT_SCALE;
        }
    }
    __syncthreads();

    if (tid < 128) {
        float* Sr = S + tid * SSTR_F;
        float mt = -1e30f, mi = -1e30f;
        for (int j = 0; j < TXT; j++) mt = fmaxf(mt, Sr[j]);
        for (int j = 80; j < 96; j++) mi = fmaxf(mi, Sr[j]);
        float lt = 0.f, li = 0.f;
        for (int j = 0; j < TXT; j++) { float e = __expf(Sr[j] - mt); lt += e; Sr[j] = e; }
        for (int j = 80; j < 96; j++) { float e = __expf(Sr[j] - mi); li += e; Sr[j] = e; }
        const float ct = ts_p[0] / lt;
        const float ci = is_p[0] / li;
        fp16* ph = sPh + tid * PSTR;
        for (int j = 0; j < 96; j++) {
            float p = (j < TXT) ? Sr[j] * ct : ((j >= 80) ? Sr[j] * ci : 0.f);
            ph[j] = __float2half_rn(p);
        }
    }
    __syncthreads();

    {
        float acc[8][4];
        #pragma unroll
        for (int n = 0; n < 8; n++)
            #pragma unroll
            for (int j = 0; j < 4; j++) acc[n][j] = 0.f;

        #pragma unroll
        for (int kk = 0; kk < 96; kk += 16) {
            uint32_t ah[4];
            ldm_x4(ah[0], ah[1], ah[2], ah[3],
                   sbase + (F_PH) * 2 + ((uint32_t)(m0w * PSTR + kk) + aoffP) * 2);
            #pragma unroll
            for (int np = 0; np < 4; np++) {
                uint32_t b0[2], b1[2];
                ldm_x4(b0[0], b0[1], b1[0], b1[1],
                       sbase + (F_V) * 2 + ((uint32_t)((np * 16) * PSTR + kk) + boffV) * 2);
                mma_f16(acc[2 * np],     ah, b0);
                mma_f16(acc[2 * np + 1], ah, b1);
            }
        }
        const size_t rg = qrow0 + m0w + grp;
        #pragma unroll
        for (int n = 0; n < 8; n++) {
            const int col = h * DH + n * 8 + 2 * t4;
            *(uint32_t*)(Aout + rg * ID + col) = pack_hi(acc[n][0], acc[n][1]);
            *(uint32_t*)(Aout + (rg + 8) * ID + col) = pack_hi(acc[n][2], acc[n][3]);
        }
    }
}

// ---------------- launch ----------------
extern "C" void kernel_launch(void* const* d_in, const int* in_sizes, int n_in,
                              void* d_out, int out_size)
{
    const float* x    = (const float*)d_in[0];
    const float* ctx  = (const float*)d_in[1];
    const float* Wq   = (const float*)d_in[2];
    const float* Wk   = (const float*)d_in[3];
    const float* Wv   = (const float*)d_in[4];
    const float* Wkip = (const float*)d_in[5];
    const float* Wvip = (const float*)d_in[6];
    const float* Wo   = (const float*)d_in[7];
    const float* bo   = (const float*)d_in[8];
    const float* ts   = (const float*)d_in[9];
    const float* isc  = (const float*)d_in[10];
    float* out = (float*)d_out;

    fp16 *gA, *gx, *gWq, *gWo, *gWc, *gct, *gci, *gKVt, *gKVi;
    cudaGetSymbolAddress((void**)&gA,   g_A);
    cudaGetSymbolAddress((void**)&gx,   g_x);
    cudaGetSymbolAddress((void**)&gWq,  g_Wq);
    cudaGetSymbolAddress((void**)&gWo,  g_Wo);
    cudaGetSymbolAddress((void**)&gWc,  g_Wc);
    cudaGetSymbolAddress((void**)&gct,  g_ct);
    cudaGetSymbolAddress((void**)&gci,  g_ci);
    cudaGetSymbolAddress((void**)&gKVt, g_KVt);
    cudaGetSymbolAddress((void**)&gKVi, g_KVi);

    cudaFuncSetAttribute(mma_gemm_kernel,
                         cudaFuncAttributeMaxDynamicSharedMemorySize, GEMM_SMEM);
    cudaFuncSetAttribute(fused_qattn_kernel,
                         cudaFuncAttributeMaxDynamicSharedMemorySize, ATT_SMEM);

    // ---- single mega-prep launch
    prep_kernel<<<(PREP_TOTAL + 255) / 256, 256>>>(
        x, Wq, Wo, Wk, Wv, Wkip, Wvip, ctx,
        gx, gWq, gWo, gWc, gct, gci);

    // ---- ctx projections: txt (z=0) + img (z=1) in ONE launch
    {
        dim3 g(KVW / 64, TXT_PAD / 128, 2);
        mma_gemm_kernel<<<g, 128, GEMM_SMEM>>>(
            gct, gWc, nullptr, gKVt, nullptr, TXT_PAD, KVW, CD,
            gci, gWc + 2 * (size_t)ID * CD, gKVi, IMG_ROWS);
    }

    // ---- fused Q-proj + attention (head fastest in grid)
    {
        dim3 g(HEADS, NQ / 128, BATCH);
        fused_qattn_kernel<<<g, AT_THREADS, ATT_SMEM>>>(gx, gWq, gKVt, gKVi,
                                                        gA, ts, isc);
    }

    // ---- out projection (fp32 + bias)
    {
        dim3 g(QD / 64, MQ / 128, 1);
        mma_gemm_kernel<<<g, 128, GEMM_SMEM>>>(gA, gWo, out, nullptr, bo,
                                               MQ, QD, ID,
                                               nullptr, nullptr, nullptr, 0);
    }
}

// round 17
// speedup vs baseline: 1.1814x; 1.0772x over previous
#include <cuda_runtime.h>
#include <cuda_fp16.h>
#include <cstdint>
#include <cstddef>

// Problem constants
#define BATCH   16
#define NQ      4096
#define QD      320
#define CD      1024
#define CTX     93
#define TXT     77
#define IMG     16
#define HEADS   8
#define DH      64
#define ID      512
#define MQ      (BATCH*NQ)
#define ATT_SCALE 0.125f

#define TXT_ROWS (BATCH*TXT)
#define TXT_PAD  1280
#define IMG_ROWS (BATCH*IMG)
#define KVW      1024

typedef __half fp16;

// ---------------- scratch ----------------
__device__ fp16 g_A  [MQ * ID];
__device__ fp16 g_x  [MQ * QD];
__device__ fp16 g_Wq [ID * QD];
__device__ fp16 g_Wo [QD * ID];
__device__ fp16 g_Wc [4][ID * CD];
__device__ fp16 g_ct [TXT_PAD * CD];
__device__ fp16 g_ci [IMG_ROWS * CD];
__device__ fp16 g_KVt[TXT_PAD * KVW];
__device__ fp16 g_KVi[IMG_ROWS * KVW];

// ---------------- helpers ----------------
__device__ __forceinline__ uint32_t smem_u32(const void* p) {
    uint32_t a;
    asm("{ .reg .u64 t; cvta.to.shared.u64 t, %1; cvt.u32.u64 %0, t; }"
        : "=r"(a) : "l"(p));
    return a;
}
__device__ __forceinline__ void cp16(uint32_t dst, const void* src) {
    asm volatile("cp.async.cg.shared.global [%0], [%1], 16;" :: "r"(dst), "l"(src));
}
#define CP_COMMIT() asm volatile("cp.async.commit_group;" ::: "memory")
#define CP_WAIT(n)  asm volatile("cp.async.wait_group %0;" :: "n"(n) : "memory")

__device__ __forceinline__ void mma_f16(float* c, const uint32_t* a, const uint32_t* b)
{
    asm volatile(
        "mma.sync.aligned.m16n8k16.row.col.f32.f16.f16.f32 "
        "{%0,%1,%2,%3}, {%4,%5,%6,%7}, {%8,%9}, {%0,%1,%2,%3};"
        : "+f"(c[0]), "+f"(c[1]), "+f"(c[2]), "+f"(c[3])
        : "r"(a[0]), "r"(a[1]), "r"(a[2]), "r"(a[3]), "r"(b[0]), "r"(b[1]));
}
__device__ __forceinline__ void ldm_x4(uint32_t& r0, uint32_t& r1,
                                       uint32_t& r2, uint32_t& r3, uint32_t addr)
{
    asm volatile("ldmatrix.sync.aligned.m8n8.x4.shared.b16 {%0,%1,%2,%3}, [%4];"
                 : "=r"(r0), "=r"(r1), "=r"(r2), "=r"(r3) : "r"(addr));
}
__device__ __forceinline__ uint32_t pack_hi(float a, float b) {
    __half2 p = __floats2half2_rn(a, b);
    return *(uint32_t*)&p;
}

// ---------------- fp16 GEMM: 128x64 tile, 128 threads, 2-stage ------------
#define GBK 32
#define SSTR 40
#define A_ELEM (128 * SSTR)
#define B_ELEM (64 * SSTR)
#define STAGE_ELEM (A_ELEM + B_ELEM)
#define NSTAGE 2
#define GEMM_SMEM (NSTAGE * STAGE_ELEM * 2)

__global__ __launch_bounds__(128, 5)
void mma_gemm_kernel(const fp16* __restrict__ Ah,
                     const fp16* __restrict__ W,
                     float* __restrict__ C, fp16* __restrict__ Ch,
                     const float* __restrict__ bias,
                     int M, int N, int K,
                     const fp16* __restrict__ A2, const fp16* __restrict__ W2,
                     fp16* __restrict__ Ch2, int M2)
{
    if (blockIdx.z == 1) {
        if ((int)blockIdx.y * 128 >= M2) return;
        Ah = A2; W = W2; Ch = Ch2; M = M2;
    }

    extern __shared__ fp16 smem[];
    const uint32_t sbase = smem_u32(smem);

    const int tid = threadIdx.x;
    const int wid = tid >> 5;
    const int lid = tid & 31;
    const int grp = lid >> 2;
    const int t4  = lid & 3;
    const int wm  = wid >> 1;
    const int wn  = wid & 1;
    const int m0  = blockIdx.y * 128;
    const int n0  = blockIdx.x * 64;

    const uint32_t aoff = (uint32_t)((lid & 15) * SSTR + (lid >> 4) * 8);
    const uint32_t boff = (uint32_t)((((lid >> 4) << 3) + (lid & 7)) * SSTR
                                     + ((lid >> 3) & 1) * 8);

    float acc[4][4][4];
    #pragma unroll
    for (int m = 0; m < 4; m++)
        #pragma unroll
        for (int n = 0; n < 4; n++)
            #pragma unroll
            for (int j = 0; j < 4; j++) acc[m][n][j] = 0.f;

    const int nch = K / GBK;

    auto load_stage = [&](int ch) {
        const int s = ch % NSTAGE;
        const int k0 = ch * GBK;
        const uint32_t base = sbase + (uint32_t)s * STAGE_ELEM * 2;
        #pragma unroll
        for (int i = 0; i < 4; i++) {
            const int c = tid + i * 128;
            const int r = c >> 2, cb = (c & 3) * 8;
            const uint32_t so = (uint32_t)(r * SSTR + cb) * 2;
            cp16(base + so, Ah + (size_t)(m0 + r) * K + k0 + cb);
        }
        #pragma unroll
        for (int i = 0; i < 2; i++) {
            const int c = tid + i * 128;
            const int r = c >> 2, cb = (c & 3) * 8;
            const uint32_t so = (uint32_t)(r * SSTR + cb) * 2;
            cp16(base + A_ELEM * 2 + so, W + (size_t)(n0 + r) * K + k0 + cb);
        }
        CP_COMMIT();
    };

    load_stage(0);
    if (nch > 1) load_stage(1);

    for (int ch = 0; ch < nch; ch++) {
        if (ch + 2 <= nch) { CP_WAIT(1); } else { CP_WAIT(0); }
        __syncthreads();

        const int s = ch % NSTAGE;
        const uint32_t Abase = sbase + (uint32_t)s * STAGE_ELEM * 2;
        const uint32_t Bbase = Abase + A_ELEM * 2;

        #pragma unroll
        for (int kk = 0; kk < GBK; kk += 16) {
            uint32_t bh[4][2];
            ldm_x4(bh[0][0], bh[0][1], bh[1][0], bh[1][1],
                   Bbase + ((uint32_t)((wn * 32) * SSTR + kk) + boff) * 2);
            ldm_x4(bh[2][0], bh[2][1], bh[3][0], bh[3][1],
                   Bbase + ((uint32_t)((wn * 32 + 16) * SSTR + kk) + boff) * 2);
            #pragma unroll
            for (int m = 0; m < 4; m++) {
                uint32_t ah[4];
                ldm_x4(ah[0], ah[1], ah[2], ah[3],
                       Abase + ((uint32_t)((wm * 64 + m * 16) * SSTR + kk) + aoff) * 2);
                #pragma unroll
                for (int n = 0; n < 4; n++)
                    mma_f16(acc[m][n], ah, bh[n]);
            }
        }
        __syncthreads();
        if (ch + 2 < nch) load_stage(ch + 2);
    }

    #pragma unroll
    for (int m = 0; m < 4; m++) {
        const int row0 = m0 + wm * 64 + m * 16 + grp;
        #pragma unroll
        for (int n = 0; n < 4; n++) {
            const int col = n0 + wn * 32 + n * 8 + t4 * 2;
            if (C) {
                float b0 = 0.f, b1 = 0.f;
                if (bias) { b0 = bias[col]; b1 = bias[col + 1]; }
                *(float2*)(C + (size_t)row0 * N + col) =
                    make_float2(acc[m][n][0] + b0, acc[m][n][1] + b1);
                *(float2*)(C + (size_t)(row0 + 8) * N + col) =
                    make_float2(acc[m][n][2] + b0, acc[m][n][3] + b1);
            } else {
                *(uint32_t*)(Ch + (size_t)row0 * N + col) = pack_hi(acc[m][n][0], acc[m][n][1]);
                *(uint32_t*)(Ch + (size_t)(row0 + 8) * N + col) = pack_hi(acc[m][n][2], acc[m][n][3]);
            }
        }
    }
}

// ---------------- prep kernel (cvt + packs, MLP=4) ----------------
// Each block covers 1024 consecutive float4 items; thread does 4 of them.
#define SEG_CVT (MQ * QD / 4)
#define SEG_PT  (TXT_PAD * CD / 4)
#define SEG_PI  (IMG_ROWS * CD / 4)
#define PREP_TOTAL (SEG_CVT + SEG_PT + SEG_PI)

__global__ __launch_bounds__(256)
void prep_kernel(const float* __restrict__ x, const float* __restrict__ ctx,
                 fp16* __restrict__ gx, fp16* __restrict__ gct,
                 fp16* __restrict__ gci)
{
    const int base = blockIdx.x * 1024 + threadIdx.x;
    #pragma unroll
    for (int it = 0; it < 4; it++) {
        int gid = base + it * 256;
        if (gid >= PREP_TOTAL) return;

        float4 v;
        uint32_t* dst;
        if (gid < SEG_CVT) {
            v = ((const float4*)x)[gid];
            dst = (uint32_t*)gx + 2 * gid;
        } else if (gid < SEG_CVT + SEG_PT) {
            const int g = gid - SEG_CVT;
            const int r = g / (CD / 4), c4 = g % (CD / 4);
            v = make_float4(0.f, 0.f, 0.f, 0.f);
            if (r < TXT_ROWS) {
                int b = r / TXT, j = r % TXT;
                v = *(const float4*)(ctx + ((size_t)b * CTX + j) * CD + c4 * 4);
            }
            dst = (uint32_t*)gct + 2 * g;
        } else {
            const int g = gid - SEG_CVT - SEG_PT;
            const int r = g / (CD / 4), c4 = g % (CD / 4);
            int b = r / IMG, j = r % IMG;
            v = *(const float4*)(ctx + ((size_t)b * CTX + TXT + j) * CD + c4 * 4);
            dst = (uint32_t*)gci + 2 * g;
        }
        dst[0] = pack_hi(v.x, v.y);
        dst[1] = pack_hi(v.z, v.w);
    }
}

// ---------------- tiled weight transpose (fp32 -> fp16, coalesced) --------
// 32x32 tiles, 256 threads (32x8). Matrices: Wq(320x512), Wo(512x320),
// Wc0..3 (1024x512 each). All dims % 32 == 0.
#define T_WQ  (10 * 16)          // 160
#define T_WO  (16 * 10)          // 160
#define T_WC  (32 * 16)          // 512 per matrix
#define T_TOTAL (T_WQ + T_WO + 4 * T_WC)

__global__ __launch_bounds__(256)
void wtrans_kernel(const float* __restrict__ Wq, const float* __restrict__ Wo,
                   const float* __restrict__ W0, const float* __restrict__ W1,
                   const float* __restrict__ W2, const float* __restrict__ W3,
                   fp16* __restrict__ gWq, fp16* __restrict__ gWo,
                   fp16* __restrict__ gWc)
{
    __shared__ float tile[32][33];

    int t = blockIdx.x;
    const float* W; fp16* D; int K, N;   // W: [K][N], D: [N][K]
    if (t < T_WQ)            { W = Wq; D = gWq; K = QD; N = ID; }
    else if ((t -= T_WQ) < T_WO) { W = Wo; D = gWo; K = ID; N = QD; }
    else {
        t -= T_WO;
        const int which = t / T_WC;
        t %= T_WC;
        W = (which == 0) ? W0 : (which == 1) ? W1 : (which == 2) ? W2 : W3;
        D = gWc + (size_t)which * ID * CD;
        K = CD; N = ID;
    }
    const int ntiles_n = N / 32;
    const int k0 = (t / ntiles_n) * 32;
    const int n0 = (t % ntiles_n) * 32;

    const int tx = threadIdx.x & 31;
    const int ty = threadIdx.x >> 5;

    #pragma unroll
    for (int i = 0; i < 4; i++) {
        const int r = ty + i * 8;
        tile[r][tx] = W[(size_t)(k0 + r) * N + n0 + tx];
    }
    __syncthreads();
    #pragma unroll
    for (int i = 0; i < 4; i++) {
        const int r = ty + i * 8;
        D[(size_t)(n0 + r) * K + k0 + tx] = __float2half_rn(tile[tx][r]);
    }
}

// ---------------- fused Q-proj + attention ----------------
#define AT_THREADS 256
#define QSTR 72
#define PSTR 104
#define SSTR_F 97
#define XSTR 40

#define F_K    0
#define F_V    (F_K + 96*QSTR)
#define F_PH   (F_V + 64*PSTR)
#define F_PIPE (F_PH + 128*PSTR)
#define XSTAGE (128*XSTR)
#define WSTAGE (64*XSTR)
#define PSTAGE (XSTAGE + WSTAGE)
#define PIPE_ELEM (3*PSTAGE)
#define S_ELEM    (128*SSTR_F*2)
#define UNION_ELEM (S_ELEM > PIPE_ELEM ? S_ELEM : PIPE_ELEM)
#define ATT_SMEM  ((F_PIPE + UNION_ELEM) * 2)

__global__ __launch_bounds__(AT_THREADS, 2)
void fused_qattn_kernel(const fp16* __restrict__ x,
                        const fp16* __restrict__ Wq,
                        const fp16* __restrict__ KVt, const fp16* __restrict__ KVi,
                        fp16* __restrict__ Aout,
                        const float* __restrict__ ts_p, const float* __restrict__ is_p)
{
    extern __shared__ fp16 sm[];
    fp16* sK  = sm + F_K;
    fp16* sV  = sm + F_V;
    fp16* sPh = sm + F_PH;
    float* S  = (float*)(sm + F_PIPE);
    const uint32_t sbase = smem_u32(sm);

    const int h = blockIdx.x, b = blockIdx.z;
    const int tid = threadIdx.x;
    const int wid = tid >> 5, lid = tid & 31;
    const int grp = lid >> 2, t4 = lid & 3;
    const int m0w = wid * 16;
    const size_t qrow0 = (size_t)b * NQ + blockIdx.y * 128;

    const uint32_t aoffX = (uint32_t)((lid & 15) * XSTR + (lid >> 4) * 8);
    const uint32_t boffX = (uint32_t)((((lid >> 4) << 3) + (lid & 7)) * XSTR
                                      + ((lid >> 3) & 1) * 8);
    const uint32_t boffK = (uint32_t)((((lid >> 4) << 3) + (lid & 7)) * QSTR
                                      + ((lid >> 3) & 1) * 8);
    const uint32_t aoffP = (uint32_t)((lid & 15) * PSTR + (lid >> 4) * 8);
    const uint32_t boffV = (uint32_t)((((lid >> 4) << 3) + (lid & 7)) * PSTR
                                      + ((lid >> 3) & 1) * 8);

    auto load_stage = [&](int ch) {
        const int s = ch % 3;
        const int k0 = ch * GBK;
        const uint32_t xb = sbase + (F_PIPE + s * PSTAGE) * 2;
        const uint32_t wb = xb + XSTAGE * 2;
        #pragma unroll
        for (int i = 0; i < 2; i++) {
            const int c = tid + i * AT_THREADS;
            const int r = c >> 2, cb = (c & 3) * 8;
            const uint32_t so = (uint32_t)(r * XSTR + cb) * 2;
            cp16(xb + so, x + (qrow0 + r) * QD + k0 + cb);
        }
        {
            const int r = tid >> 2, cb = (tid & 3) * 8;
            const uint32_t so = (uint32_t)(r * XSTR + cb) * 2;
            cp16(wb + so, Wq + (size_t)(h * DH + r) * QD + k0 + cb);
        }
        CP_COMMIT();
    };

    load_stage(0);
    load_stage(1);
    load_stage(2);

    // stage K (96 rows, zero pad 77..79): uint4 copies
    for (int i = tid; i < 96 * 8; i += AT_THREADS) {
        const int r = i >> 3, c = i & 7;
        uint4 vk = make_uint4(0, 0, 0, 0);
        if (r < TXT) {
            vk = *(const uint4*)(KVt + ((size_t)b * TXT + r) * KVW + h * DH + c * 8);
        } else if (r >= 80) {
            vk = *(const uint4*)(KVi + ((size_t)b * IMG + (r - 80)) * KVW + h * DH + c * 8);
        }
        *(uint4*)(sK + r * QSTR + c * 8) = vk;
    }
    // stage V transposed: uint4 global loads (8 d's per thread-item)
    for (int i = tid; i < 96 * 8; i += AT_THREADS) {
        const int j = i >> 3, d8 = (i & 7) * 8;
        uint4 vv = make_uint4(0, 0, 0, 0);
        if (j < TXT) {
            vv = *(const uint4*)(KVt + ((size_t)b * TXT + j) * KVW + 512 + h * DH + d8);
        } else if (j >= 80) {
            vv = *(const uint4*)(KVi + ((size_t)b * IMG + (j - 80)) * KVW + 512 + h * DH + d8);
        }
        const fp16* pv = (const fp16*)&vv;
        #pragma unroll
        for (int u = 0; u < 8; u++)
            sV[(d8 + u) * PSTR + j] = pv[u];
    }

    float qacc[8][4];
    #pragma unroll
    for (int n = 0; n < 8; n++)
        #pragma unroll
        for (int j = 0; j < 4; j++) qacc[n][j] = 0.f;

    const int nch = QD / GBK;   // 10
    for (int ch = 0; ch < nch; ch++) {
        if (ch + 3 <= nch)      { CP_WAIT(2); }
        else if (ch + 2 <= nch) { CP_WAIT(1); }
        else                    { CP_WAIT(0); }
        __syncthreads();

        const int s = ch % 3;
        const uint32_t Xbase = sbase + (F_PIPE + s * PSTAGE) * 2;
        const uint32_t Wbase = Xbase + XSTAGE * 2;

        #pragma unroll
        for (int kk = 0; kk < GBK; kk += 16) {
            uint32_t ah[4];
            ldm_x4(ah[0], ah[1], ah[2], ah[3],
                   Xbase + ((uint32_t)(m0w * XSTR + kk) + aoffX) * 2);
            #pragma unroll
            for (int np = 0; np < 4; np++) {
                uint32_t b0[2], b1[2];
                ldm_x4(b0[0], b0[1], b1[0], b1[1],
                       Wbase + ((uint32_t)((np * 16) * XSTR + kk) + boffX) * 2);
                mma_f16(qacc[2 * np],     ah, b0);
                mma_f16(qacc[2 * np + 1], ah, b1);
            }
        }
        __syncthreads();
        if (ch + 3 < nch) load_stage(ch + 3);
    }

    uint32_t qah[4][4];
    #pragma unroll
    for (int i = 0; i < 4; i++) {
        qah[i][0] = pack_hi(qacc[2*i][0], qacc[2*i][1]);
        qah[i][1] = pack_hi(qacc[2*i][2], qacc[2*i][3]);
        qah[i][2] = pack_hi(qacc[2*i+1][0], qacc[2*i+1][1]);
        qah[i][3] = pack_hi(qacc[2*i+1][2], qacc[2*i+1][3]);
    }

    {
        float acc[12][4];
        #pragma unroll
        for (int n = 0; n < 12; n++)
            #pragma unroll
            for (int j = 0; j < 4; j++) acc[n][j] = 0.f;

        #pragma unroll
        for (int i = 0; i < 4; i++) {
            const int kk = i * 16;
            #pragma unroll
            for (int np = 0; np < 6; np++) {
                uint32_t b0[2], b1[2];
                ldm_x4(b0[0], b0[1], b1[0], b1[1],
                       sbase + (F_K) * 2 + ((uint32_t)((np * 16) * QSTR + kk) + boffK) * 2);
                mma_f16(acc[2 * np],     qah[i], b0);
                mma_f16(acc[2 * np + 1], qah[i], b1);
            }
        }
        #pragma unroll
        for (int n = 0; n < 12; n++) {
            const int cb = n * 8 + 2 * t4;
            S[(m0w + grp) * SSTR_F + cb]     = acc[n][0] * ATT_SCALE;
            S[(m0w + grp) * SSTR_F + cb + 1] = acc[n][1] * ATT_SCALE;
            S[(m0w + grp + 8) * SSTR_F + cb]     = acc[n][2] * ATT_SCALE;
            S[(m0w + grp + 8) * SSTR_F + cb + 1] = acc[n][3] * ATT_SCALE;
        }
    }
    __syncthreads();

    if (tid < 128) {
        float* Sr = S + tid * SSTR_F;
        float mt = -1e30f, mi = -1e30f;
        for (int j = 0; j < TXT; j++) mt = fmaxf(mt, Sr[j]);
        for (int j = 80; j < 96; j++) mi = fmaxf(mi, Sr[j]);
        float lt = 0.f, li = 0.f;
        for (int j = 0; j < TXT; j++) { float e = __expf(Sr[j] - mt); lt += e; Sr[j] = e; }
        for (int j = 80; j < 96; j++) { float e = __expf(Sr[j] - mi); li += e; Sr[j] = e; }
        const float ct = ts_p[0] / lt;
        const float ci = is_p[0] / li;
        fp16* ph = sPh + tid * PSTR;
        for (int j = 0; j < 96; j++) {
            float p = (j < TXT) ? Sr[j] * ct : ((j >= 80) ? Sr[j] * ci : 0.f);
            ph[j] = __float2half_rn(p);
        }
    }
    __syncthreads();

    {
        float acc[8][4];
        #pragma unroll
        for (int n = 0; n < 8; n++)
            #pragma unroll
            for (int j = 0; j < 4; j++) acc[n][j] = 0.f;

        #pragma unroll
        for (int kk = 0; kk < 96; kk += 16) {
            uint32_t ah[4];
            ldm_x4(ah[0], ah[1], ah[2], ah[3],
                   sbase + (F_PH) * 2 + ((uint32_t)(m0w * PSTR + kk) + aoffP) * 2);
            #pragma unroll
            for (int np = 0; np < 4; np++) {
                uint32_t b0[2], b1[2];
                ldm_x4(b0[0], b0[1], b1[0], b1[1],
                       sbase + (F_V) * 2 + ((uint32_t)((np * 16) * PSTR + kk) + boffV) * 2);
                mma_f16(acc[2 * np],     ah, b0);
                mma_f16(acc[2 * np + 1], ah, b1);
            }
        }
        const size_t rg = qrow0 + m0w + grp;
        #pragma unroll
        for (int n = 0; n < 8; n++) {
            const int col = h * DH + n * 8 + 2 * t4;
            *(uint32_t*)(Aout + rg * ID + col) = pack_hi(acc[n][0], acc[n][1]);
            *(uint32_t*)(Aout + (rg + 8) * ID + col) = pack_hi(acc[n][2], acc[n][3]);
        }
    }
}

// ---------------- launch ----------------
extern "C" void kernel_launch(void* const* d_in, const int* in_sizes, int n_in,
                              void* d_out, int out_size)
{
    const float* x    = (const float*)d_in[0];
    const float* ctx  = (const float*)d_in[1];
    const float* Wq   = (const float*)d_in[2];
    const float* Wk   = (const float*)d_in[3];
    const float* Wv   = (const float*)d_in[4];
    const float* Wkip = (const float*)d_in[5];
    const float* Wvip = (const float*)d_in[6];
    const float* Wo   = (const float*)d_in[7];
    const float* bo   = (const float*)d_in[8];
    const float* ts   = (const float*)d_in[9];
    const float* isc  = (const float*)d_in[10];
    float* out = (float*)d_out;

    fp16 *gA, *gx, *gWq, *gWo, *gWc, *gct, *gci, *gKVt, *gKVi;
    cudaGetSymbolAddress((void**)&gA,   g_A);
    cudaGetSymbolAddress((void**)&gx,   g_x);
    cudaGetSymbolAddress((void**)&gWq,  g_Wq);
    cudaGetSymbolAddress((void**)&gWo,  g_Wo);
    cudaGetSymbolAddress((void**)&gWc,  g_Wc);
    cudaGetSymbolAddress((void**)&gct,  g_ct);
    cudaGetSymbolAddress((void**)&gci,  g_ci);
    cudaGetSymbolAddress((void**)&gKVt, g_KVt);
    cudaGetSymbolAddress((void**)&gKVi, g_KVi);

    cudaFuncSetAttribute(mma_gemm_kernel,
                         cudaFuncAttributeMaxDynamicSharedMemorySize, GEMM_SMEM);
    cudaFuncSetAttribute(fused_qattn_kernel,
                         cudaFuncAttributeMaxDynamicSharedMemorySize, ATT_SMEM);

    // ---- prep: tiled W transposes + cvt/pack (2 launches)
    wtrans_kernel<<<T_TOTAL, 256>>>(Wq, Wo, Wk, Wv, Wkip, Wvip, gWq, gWo, gWc);
    prep_kernel<<<(PREP_TOTAL + 1023) / 1024, 256>>>(x, ctx, gx, gct, gci);

    // ---- ctx projections: txt (z=0) + img (z=1) in ONE launch
    {
        dim3 g(KVW / 64, TXT_PAD / 128, 2);
        mma_gemm_kernel<<<g, 128, GEMM_SMEM>>>(
            gct, gWc, nullptr, gKVt, nullptr, TXT_PAD, KVW, CD,
            gci, gWc + 2 * (size_t)ID * CD, gKVi, IMG_ROWS);
    }

    // ---- fused Q-proj + attention (head fastest in grid)
    {
        dim3 g(HEADS, NQ / 128, BATCH);
        fused_qattn_kernel<<<g, AT_THREADS, ATT_SMEM>>>(gx, gWq, gKVt, gKVi,
                                                        gA, ts, isc);
    }

    // ---- out projection (fp32 + bias)
    {
        dim3 g(QD / 64, MQ / 128, 1);
        mma_gemm_kernel<<<g, 128, GEMM_SMEM>>>(gA, gWo, out, nullptr, bo,
                                               MQ, QD, ID,
                                               nullptr, nullptr, nullptr, 0);
    }
}